// round 16
// baseline (speedup 1.0000x reference)
#include <cuda_runtime.h>
#include <cuda_bf16.h>

#define USER_NUM 200000
#define ITEM_NUM 100000
#define EMB 64
#define MAX_NE 3200000
#define NB_SCAN ((USER_NUM + 1023) / 1024)   // 196

// ---------------------------------------------------------------------------
// Scratch (__device__ globals; no allocation allowed)
// ---------------------------------------------------------------------------
__device__ float g_agg[(size_t)USER_NUM * EMB];     // 51.2 MB
__device__ float g_U[(size_t)USER_NUM * EMB];       // 51.2 MB
// CSR(S)
__device__ int   g_ccolS[MAX_NE];
__device__ float g_cvalS[MAX_NE];
__device__ int   g_cntS[USER_NUM];
__device__ int   g_rsS[USER_NUM];
__device__ int   g_curS[USER_NUM];
__device__ int   g_bsumS[256];
// CSR(R)
__device__ int   g_ccolR[MAX_NE];
__device__ float g_cvalR[MAX_NE];
__device__ int   g_cntR[USER_NUM];
__device__ int   g_rsR[USER_NUM];
__device__ int   g_curR[USER_NUM];
__device__ int   g_bsumR[256];

// ---------------------------------------------------------------------------
// Fused dual-matrix CSR build kernels (unchanged from R15 best)
// ---------------------------------------------------------------------------
__global__ void zero2_kernel(int* __restrict__ pS, int* __restrict__ pR, int n) {
    int i = blockIdx.x * blockDim.x + threadIdx.x;
    if (i < n)          pS[i] = 0;
    else if (i < 2 * n) pR[i - n] = 0;
}

__global__ void hist2_kernel(const int* __restrict__ rowsS, int* __restrict__ cntS, int neS,
                             const int* __restrict__ rowsR, int* __restrict__ cntR, int neR) {
    int i = blockIdx.x * blockDim.x + threadIdx.x;
    if (i < neS)              atomicAdd(&cntS[rowsS[i]], 1);
    else if (i - neS < neR)   atomicAdd(&cntR[rowsR[i - neS]], 1);
}

__device__ __forceinline__ int warp_excl_scan(int v, int lane, int* total) {
    int x = v;
    #pragma unroll
    for (int d = 1; d < 32; d <<= 1) {
        int y = __shfl_up_sync(0xffffffffu, x, d);
        if (lane >= d) x += y;
    }
    *total = __shfl_sync(0xffffffffu, x, 31);
    return x - v;
}

__global__ void block_sum2_kernel(const int* __restrict__ cntS, int* __restrict__ bsumS,
                                  const int* __restrict__ cntR, int* __restrict__ bsumR,
                                  int n) {
    __shared__ int wsum[8];
    int tid = threadIdx.x, lane = tid & 31, wid = tid >> 5;
    int bb = blockIdx.x;
    const int* cnt  = (bb < NB_SCAN) ? cntS  : cntR;
    int*       bsum = (bb < NB_SCAN) ? bsumS : bsumR;
    int blk = (bb < NB_SCAN) ? bb : bb - NB_SCAN;

    int base = blk * 1024 + tid * 4;
    int s = 0;
    #pragma unroll
    for (int j = 0; j < 4; j++) { int idx = base + j; if (idx < n) s += cnt[idx]; }
    int tot; warp_excl_scan(s, lane, &tot);
    if (lane == 31) wsum[wid] = tot;
    __syncthreads();
    if (tid == 0) {
        int t = 0;
        #pragma unroll
        for (int w = 0; w < 8; w++) t += wsum[w];
        bsum[blk] = t;
    }
}

__global__ void scan_bsum2_kernel(int* __restrict__ bsumS, int* __restrict__ bsumR, int nb) {
    __shared__ int wsum[8];
    int tid = threadIdx.x, lane = tid & 31, wid = tid >> 5;
    int* bsum = (blockIdx.x == 0) ? bsumS : bsumR;
    int v = (tid < nb) ? bsum[tid] : 0;
    int wtot; int ex = warp_excl_scan(v, lane, &wtot);
    if (lane == 31) wsum[wid] = wtot;
    __syncthreads();
    if (wid == 0) {
        int t = (lane < 8) ? wsum[lane] : 0;
        int tt; int e = warp_excl_scan(t, lane, &tt);
        if (lane < 8) wsum[lane] = e;
    }
    __syncthreads();
    if (tid < nb) bsum[tid] = wsum[wid] + ex;
}

__global__ void scan_block2_kernel(const int* __restrict__ cntS, const int* __restrict__ boffS,
                                   int* __restrict__ rsS, int* __restrict__ curS,
                                   const int* __restrict__ cntR, const int* __restrict__ boffR,
                                   int* __restrict__ rsR, int* __restrict__ curR,
                                   int n) {
    __shared__ int wsum[8];
    int tid = threadIdx.x, lane = tid & 31, wid = tid >> 5;
    int bb = blockIdx.x;
    bool isS = (bb < NB_SCAN);
    const int* cnt  = isS ? cntS  : cntR;
    const int* boff = isS ? boffS : boffR;
    int* rs  = isS ? rsS  : rsR;
    int* cur = isS ? curS : curR;
    int blk = isS ? bb : bb - NB_SCAN;

    int base = blk * 1024 + tid * 4;
    int v[4]; int s = 0;
    #pragma unroll
    for (int j = 0; j < 4; j++) { int idx = base + j; v[j] = (idx < n) ? cnt[idx] : 0; s += v[j]; }
    int wtot; int ex = warp_excl_scan(s, lane, &wtot);
    if (lane == 31) wsum[wid] = wtot;
    __syncthreads();
    if (wid == 0) {
        int t = (lane < 8) ? wsum[lane] : 0;
        int tt; int e = warp_excl_scan(t, lane, &tt);
        if (lane < 8) wsum[lane] = e;
    }
    __syncthreads();
    int off = boff[blk] + wsum[wid] + ex;
    #pragma unroll
    for (int j = 0; j < 4; j++) {
        int idx = base + j;
        if (idx < n) { rs[idx] = off; cur[idx] = off; off += v[j]; }
    }
}

__global__ void scatter2_kernel(const int* __restrict__ rowsS, const int* __restrict__ colsS,
                                const float* __restrict__ valsS, int* __restrict__ curS,
                                int* __restrict__ ccolS, float* __restrict__ cvalS, int neS,
                                const int* __restrict__ rowsR, const int* __restrict__ colsR,
                                const float* __restrict__ valsR, int* __restrict__ curR,
                                int* __restrict__ ccolR, float* __restrict__ cvalR, int neR) {
    int i = blockIdx.x * blockDim.x + threadIdx.x;
    if (i < neS) {
        int r = rowsS[i];
        int p = atomicAdd(&curS[r], 1);
        ccolS[p] = colsS[i];
        cvalS[p] = valsS[i];
    } else if (i - neS < neR) {
        int j = i - neS;
        int r = rowsR[j];
        int p = atomicAdd(&curR[r], 1);
        ccolR[p] = colsR[j];
        cvalR[p] = valsR[j];
    }
}

// ---------------------------------------------------------------------------
// CSR SpMM (identical to R2): 16 threads/row, register accumulation
// ---------------------------------------------------------------------------
__global__ void __launch_bounds__(256)
spmm_csr_kernel(const int* __restrict__ rs, const int* __restrict__ cnt,
                const int* __restrict__ ccol, const float* __restrict__ cval,
                const float4* __restrict__ X4, float4* __restrict__ out4,
                int accumulate) {
    long long t = (long long)blockIdx.x * blockDim.x + threadIdx.x;
    int row = (int)(t >> 4);
    int g   = (int)(t & 15);
    if (row >= USER_NUM) return;
    int s = rs[row];
    int e = s + cnt[row];
    float4 acc;
    if (accumulate) acc = out4[(long long)row * 16 + g];
    else            acc = make_float4(0.f, 0.f, 0.f, 0.f);
    for (int i = s; i < e; i++) {
        int   c = __ldg(&ccol[i]);
        float v = __ldg(&cval[i]);
        float4 x = X4[(long long)c * 16 + g];
        acc.x += v * x.x; acc.y += v * x.y; acc.z += v * x.z; acc.w += v * x.w;
    }
    out4[(long long)row * 16 + g] = acc;
}

// ---------------------------------------------------------------------------
// Packed-FFMA2 GEMM + bias + ReLU.
//   out[r,o] = relu( sum_k h[r,k]*W[o,k] + b[o] ),  h = concat(agg, U)
// Block 256 rows x 64 outs, 256 threads, thread tile 8r x 8o (pairs over o).
//   ws[k][o] o-contiguous -> (W[o0,k],W[o1,k]) pairs from one LDS.128 (free)
//   hs[r][k] row-major    -> h scalars via 8-lane-broadcast LDS.32
//   (h,h) dup built in registers (1 mov.b64), NOT in smem (R3's mistake:
//    smem dup made it crossbar-bound at 144us/layer)
// Per k/thread: 2 LDS.128 + 8 LDS.32 + 8 MOV + 32 FFMA2  -> FFMA-pipe bound.
// ---------------------------------------------------------------------------
#define HS_STRIDE 132
#define WS_STRIDE 68
#define GEMM_SMEM ((256 * HS_STRIDE + 128 * WS_STRIDE) * 4)   // 169,984 B

__device__ __forceinline__ void fma2(unsigned long long& d,
                                     unsigned long long a,
                                     unsigned long long b) {
    asm("fma.rn.f32x2 %0, %1, %2, %0;" : "+l"(d) : "l"(a), "l"(b));
}
__device__ __forceinline__ unsigned long long dup_f(float x) {
    unsigned long long p;
    asm("mov.b64 %0, {%1, %1};" : "=l"(p) : "r"(__float_as_uint(x)));
    return p;
}

__global__ void __launch_bounds__(256, 1)
gemm_relu_kernel(const float4* __restrict__ agg4,
                 const float4* __restrict__ u4,
                 const float4* __restrict__ W4,   // [64][32] float4 view of [64][128]
                 const float*  __restrict__ bias,
                 float4* __restrict__ out4) {
    extern __shared__ float smem[];
    float* hs = smem;                         // 256 x 132
    float* ws = smem + 256 * HS_STRIDE;       // 128 x 68

    int tid = threadIdx.x;
    long long block_row = (long long)blockIdx.x * 256;

    // ---- stage h tile: 256 rows x 32 float4 (agg cols 0..15, U cols 16..31) ----
    #pragma unroll
    for (int i = tid; i < 256 * 32; i += 256) {
        int r = i >> 5, c = i & 31;
        long long grow = block_row + r;
        float4 v = make_float4(0.f, 0.f, 0.f, 0.f);
        if (grow < USER_NUM)
            v = (c < 16) ? agg4[grow * 16 + c] : u4[grow * 16 + (c - 16)];
        *(float4*)&hs[r * HS_STRIDE + c * 4] = v;
    }
    // ---- stage W transposed: ws[k][o] = W[o][k] ----
    #pragma unroll
    for (int i = tid; i < 64 * 32; i += 256) {
        int o = i & 63, c = i >> 6;
        float4 w = W4[o * 32 + c];
        ws[(4 * c + 0) * WS_STRIDE + o] = w.x;
        ws[(4 * c + 1) * WS_STRIDE + o] = w.y;
        ws[(4 * c + 2) * WS_STRIDE + o] = w.z;
        ws[(4 * c + 3) * WS_STRIDE + o] = w.w;
    }
    __syncthreads();

    // thread tile: rows 32*wy + ty + 4*j (j=0..7), outs 8*tx..8*tx+7
    int tx = tid & 7;            // o-group
    int ty = (tid >> 3) & 3;     // row interleave (bank-spread)
    int wy = tid >> 5;           // warp row-slab
    int rbase = 32 * wy + ty;
    int o0 = 8 * tx;

    unsigned long long acc[8][4] = {};   // [row j][o-pair]

    #pragma unroll 4
    for (int k = 0; k < 128; k++) {
        // W pairs: (o0,o1),(o2,o3) and (o4,o5),(o6,o7) — two LDS.128
        ulonglong2 wpA = *(const ulonglong2*)&ws[k * WS_STRIDE + o0];
        ulonglong2 wpB = *(const ulonglong2*)&ws[k * WS_STRIDE + o0 + 4];
        #pragma unroll
        for (int j = 0; j < 8; j++) {
            unsigned long long hp = dup_f(hs[(rbase + 4 * j) * HS_STRIDE + k]);
            fma2(acc[j][0], hp, wpA.x);
            fma2(acc[j][1], hp, wpA.y);
            fma2(acc[j][2], hp, wpB.x);
            fma2(acc[j][3], hp, wpB.y);
        }
    }

    // ---- epilogue: bias + relu, guarded stores ----
    float4 ba = *(const float4*)&bias[o0];
    float4 bb = *(const float4*)&bias[o0 + 4];
    #pragma unroll
    for (int j = 0; j < 8; j++) {
        long long r = block_row + rbase + 4 * j;
        if (r < USER_NUM) {
            float4 v0, v1;
            v0.x = fmaxf(__uint_as_float((unsigned int)(acc[j][0]))       + ba.x, 0.f);
            v0.y = fmaxf(__uint_as_float((unsigned int)(acc[j][0] >> 32)) + ba.y, 0.f);
            v0.z = fmaxf(__uint_as_float((unsigned int)(acc[j][1]))       + ba.z, 0.f);
            v0.w = fmaxf(__uint_as_float((unsigned int)(acc[j][1] >> 32)) + ba.w, 0.f);
            v1.x = fmaxf(__uint_as_float((unsigned int)(acc[j][2]))       + bb.x, 0.f);
            v1.y = fmaxf(__uint_as_float((unsigned int)(acc[j][2] >> 32)) + bb.y, 0.f);
            v1.z = fmaxf(__uint_as_float((unsigned int)(acc[j][3]))       + bb.z, 0.f);
            v1.w = fmaxf(__uint_as_float((unsigned int)(acc[j][3] >> 32)) + bb.w, 0.f);
            out4[r * 16 + 2 * tx]     = v0;
            out4[r * 16 + 2 * tx + 1] = v1;
        }
    }
}

// ---------------------------------------------------------------------------
// Launch: fully serial on stream 0 (R15 structure, proven best)
// ---------------------------------------------------------------------------
extern "C" void kernel_launch(void* const* d_in, const int* in_sizes, int n_in,
                              void* d_out, int out_size) {
    const float* user_emb = (const float*)d_in[0];
    const float* item_emb = (const float*)d_in[1];
    const float* W        = (const float*)d_in[2];
    const float* b        = (const float*)d_in[3];
    const int*   s_rows   = (const int*)  d_in[4];
    const int*   s_cols   = (const int*)  d_in[5];
    const float* s_vals   = (const float*)d_in[6];
    const int*   r_rows   = (const int*)  d_in[7];
    const int*   r_cols   = (const int*)  d_in[8];
    const float* r_vals   = (const float*)d_in[9];
    int ne_s = in_sizes[4];
    int ne_r = in_sizes[7];

    float* out_user = (float*)d_out;
    float* out_item = out_user + (size_t)USER_NUM * EMB;

    float *agg, *U1, *cvalS, *cvalR;
    int *cntS, *rsS, *curS, *bsumS, *ccolS;
    int *cntR, *rsR, *curR, *bsumR, *ccolR;
    cudaGetSymbolAddress((void**)&agg,   g_agg);
    cudaGetSymbolAddress((void**)&U1,    g_U);
    cudaGetSymbolAddress((void**)&cntS,  g_cntS);
    cudaGetSymbolAddress((void**)&rsS,   g_rsS);
    cudaGetSymbolAddress((void**)&curS,  g_curS);
    cudaGetSymbolAddress((void**)&bsumS, g_bsumS);
    cudaGetSymbolAddress((void**)&ccolS, g_ccolS);
    cudaGetSymbolAddress((void**)&cvalS, g_cvalS);
    cudaGetSymbolAddress((void**)&cntR,  g_cntR);
    cudaGetSymbolAddress((void**)&rsR,   g_rsR);
    cudaGetSymbolAddress((void**)&curR,  g_curR);
    cudaGetSymbolAddress((void**)&bsumR, g_bsumR);
    cudaGetSymbolAddress((void**)&ccolR, g_ccolR);
    cudaGetSymbolAddress((void**)&cvalR, g_cvalR);

    cudaFuncSetAttribute(gemm_relu_kernel,
                         cudaFuncAttributeMaxDynamicSharedMemorySize, GEMM_SMEM);

    const int spmm_gb = (USER_NUM * 16 + 255) / 256;            // 12500
    const int gemm_gb = (USER_NUM + 255) / 256;                 // 782
    const int zb2     = (2 * USER_NUM + 255) / 256;
    const int hb2     = (ne_s + ne_r + 255) / 256;

    // item_all = V (independent; front-load)
    cudaMemcpyAsync(out_item, item_emb, (size_t)ITEM_NUM * EMB * sizeof(float),
                    cudaMemcpyDeviceToDevice, 0);

    // ---- Fused CSR build for S and R ----
    zero2_kernel<<<zb2, 256>>>(cntS, cntR, USER_NUM);
    hist2_kernel<<<hb2, 256>>>(s_rows, cntS, ne_s, r_rows, cntR, ne_r);
    block_sum2_kernel<<<2 * NB_SCAN, 256>>>(cntS, bsumS, cntR, bsumR, USER_NUM);
    scan_bsum2_kernel<<<2, 256>>>(bsumS, bsumR, NB_SCAN);
    scan_block2_kernel<<<2 * NB_SCAN, 256>>>(cntS, bsumS, rsS, curS,
                                             cntR, bsumR, rsR, curR, USER_NUM);
    scatter2_kernel<<<hb2, 256>>>(s_rows, s_cols, s_vals, curS, ccolS, cvalS, ne_s,
                                  r_rows, r_cols, r_vals, curR, ccolR, cvalR, ne_r);

    // ---- Layer 0 ----
    spmm_csr_kernel<<<spmm_gb, 256>>>(rsS, cntS, ccolS, cvalS,
                                      (const float4*)user_emb, (float4*)agg, 0);
    gemm_relu_kernel<<<gemm_gb, 256, GEMM_SMEM>>>((const float4*)agg,
                                                  (const float4*)user_emb,
                                                  (const float4*)W, b, (float4*)U1);
    // ---- Layer 1 ----
    spmm_csr_kernel<<<spmm_gb, 256>>>(rsS, cntS, ccolS, cvalS,
                                      (const float4*)U1, (float4*)agg, 0);
    gemm_relu_kernel<<<gemm_gb, 256, GEMM_SMEM>>>((const float4*)agg,
                                                  (const float4*)U1,
                                                  (const float4*)(W + 64 * 128), b + 64,
                                                  (float4*)out_user);

    // ---- Final accumulate: out_user += R @ V ----
    spmm_csr_kernel<<<spmm_gb, 256>>>(rsR, cntR, ccolR, cvalR,
                                      (const float4*)item_emb, (float4*)out_user, 1);
}